// round 16
// baseline (speedup 1.0000x reference)
#include <cuda_runtime.h>
#include <cuda_fp16.h>
#include <cstdint>

// Problem constants (fixed shapes per reference setup_inputs)
#define Bn      8
#define Nn      8192
#define Cn      64
#define NP      2048
#define NS      32
#define CIN     67
#define H1n     64
#define H2n     128
#define RADIUS2 0.01f

#define GRID    8
#define NCELL   (GRID * GRID * GRID)     // 512 per batch
#define CAND_MAX 288
#define NCTA    296                      // persistent: 2 CTAs x 148 SMs

// Scratch (allocation-free rule: __device__ globals)
__device__ __half g_featTh[(size_t)Bn * Nn * Cn];      // 8 MB, (B,N,C) fp16
__device__ float4 g_pts[Bn * Nn];                      // 1 MB cell-sorted pts
__device__ int    g_cellCount[Bn * NCELL];
__device__ int    g_cellStart[Bn * NCELL];

typedef unsigned long long ull;

// ---------------------------------------------------------------------------
// fp16 mma / ldmatrix helpers
// ---------------------------------------------------------------------------
__device__ __forceinline__ void mma_f16(float c[4], const unsigned a[4],
                                        unsigned b0, unsigned b1)
{
    asm volatile(
        "mma.sync.aligned.m16n8k16.row.col.f32.f16.f16.f32 "
        "{%0,%1,%2,%3}, {%4,%5,%6,%7}, {%8,%9}, {%0,%1,%2,%3};"
        : "+f"(c[0]), "+f"(c[1]), "+f"(c[2]), "+f"(c[3])
        : "r"(a[0]), "r"(a[1]), "r"(a[2]), "r"(a[3]), "r"(b0), "r"(b1));
}

__device__ __forceinline__ void ldsm4(unsigned* r, unsigned addr)
{
    asm volatile("ldmatrix.sync.aligned.m8n8.x4.shared.b16 {%0,%1,%2,%3}, [%4];"
                 : "=r"(r[0]), "=r"(r[1]), "=r"(r[2]), "=r"(r[3]) : "r"(addr));
}

__device__ __forceinline__ unsigned h2pack(float lo, float hi)
{
    __half2 h = __floats2half2_rn(lo, hi);
    return *(unsigned*)&h;
}

__device__ __forceinline__ int cell_of(float x, float y, float z)
{
    int cx = min(GRID - 1, max(0, (int)(x * (float)GRID)));
    int cy = min(GRID - 1, max(0, (int)(y * (float)GRID)));
    int cz = min(GRID - 1, max(0, (int)(z * (float)GRID)));
    return cx + GRID * (cy + GRID * cz);
}

// ---------------------------------------------------------------------------
// Single-kernel binning: one 1024-thread CTA per batch.
// ---------------------------------------------------------------------------
__global__ __launch_bounds__(1024) void bin_all_kernel(
    const float* __restrict__ xyz,
    float4* __restrict__ pts,
    int* __restrict__ cellStart, int* __restrict__ cellCount)
{
    __shared__ int sc[NCELL];
    __shared__ int scur[NCELL];

    const int b = blockIdx.x;
    const int t = threadIdx.x;          // 0..1023, 8 points per thread

    if (t < NCELL) sc[t] = 0;
    __syncthreads();

    const float* xb = xyz + (size_t)b * Nn * 3;
    float px[8], py[8], pz[8];
    int   pc[8];

    #pragma unroll
    for (int j = 0; j < 8; j++) {
        int i = t + j * 1024;
        px[j] = xb[i * 3 + 0];
        py[j] = xb[i * 3 + 1];
        pz[j] = xb[i * 3 + 2];
        pc[j] = cell_of(px[j], py[j], pz[j]);
        atomicAdd(&sc[pc[j]], 1);
    }
    __syncthreads();

    int c0 = (t < NCELL) ? sc[t] : 0;
    for (int off = 1; off < NCELL; off <<= 1) {
        int v = 0;
        if (t < NCELL && t >= off) v = sc[t - off];
        __syncthreads();
        if (t < NCELL) sc[t] += v;
        __syncthreads();
    }
    if (t < NCELL) {
        int excl = sc[t] - c0;
        cellStart[b * NCELL + t] = excl;
        cellCount[b * NCELL + t] = c0;
        scur[t] = excl;
    }
    __syncthreads();

    float4* pout = pts + (size_t)b * Nn;
    #pragma unroll
    for (int j = 0; j < 8; j++) {
        int i = t + j * 1024;
        int pos = atomicAdd(&scur[pc[j]], 1);
        pout[pos] = make_float4(px[j], py[j], pz[j], __int_as_float(i));
    }
}

// ---------------------------------------------------------------------------
// Transpose features (B,C,N) f32 -> (B,N,C) fp16, vectorized.
// ---------------------------------------------------------------------------
__global__ __launch_bounds__(256) void transpose_kernel(
    const float* __restrict__ f, __half* __restrict__ ft)
{
    __shared__ float tile[64][33];
    const int b  = blockIdx.z;
    const int c0 = blockIdx.y * 32;
    const int n0 = blockIdx.x * 64;
    const int t  = threadIdx.x;

    const float* fb = f + (size_t)b * Cn * Nn;

    #pragma unroll
    for (int j = 0; j < 2; j++) {
        int idx = t + j * 256;
        int c   = idx >> 4;
        int n4  = (idx & 15) * 4;
        float4 v = __ldg((const float4*)&fb[(size_t)(c0 + c) * Nn + n0 + n4]);
        tile[n4 + 0][c] = v.x;
        tile[n4 + 1][c] = v.y;
        tile[n4 + 2][c] = v.z;
        tile[n4 + 3][c] = v.w;
    }
    __syncthreads();

    __half* fo = ft + (size_t)b * Nn * Cn;
    #pragma unroll
    for (int j = 0; j < 2; j++) {
        int idx = t + j * 256;
        int n   = idx >> 3;
        int c4  = (idx & 7) * 4;
        unsigned lo = h2pack(tile[n][c4 + 0], tile[n][c4 + 1]);
        unsigned hi = h2pack(tile[n][c4 + 2], tile[n][c4 + 3]);
        ull pk = (ull)lo | ((ull)hi << 32);
        *(ull*)&fo[(size_t)(n0 + n) * Cn + c0 + c4] = pk;
    }
}

// ---------------------------------------------------------------------------
// FUSED persistent kernel: grid ball query + group + MLP + max.
// R16: 2-stage pipeline — ball query of query i+1 (scan, batched candidate
// loads, selection, staging) interleaved with query i's layer-2 MMAs, which
// are split into 4 quarters of 32 outputs so candidate batches drain under
// tensor work. Loop steady state starts directly at layer-1.
// ---------------------------------------------------------------------------
#define A_STR   88
#define W1_STR  88
#define W2_STR  72
#define A_OFF   0
#define W1_OFF  (256 * A_STR)               // 22528 halfs
#define W2_OFF  (W1_OFF + 64 * W1_STR)      // 28160
#define HALF_END (W2_OFF + 128 * W2_STR)    // 37376 halfs = 74752 B
#define BIAS_BYTES ((64 + 128) * 4)
#define CBUF_OFF_B (HALF_END * 2 + BIAS_BYTES)
#define SMEM_BYTES (CBUF_OFF_B + 8 * CAND_MAX * 4)

__global__ __launch_bounds__(256, 2) void fused_kernel(
    const float*  __restrict__ xyz,
    const float4* __restrict__ pts,
    const int*    __restrict__ cellStart,
    const int*    __restrict__ cellCount,
    const float*  __restrict__ W1,
    const float*  __restrict__ b1,
    const float*  __restrict__ W2,
    const float*  __restrict__ b2,
    float* __restrict__ out)
{
    extern __shared__ __half smh[];
    __half* Ah  = smh + A_OFF;
    __half* w1s = smh + W1_OFF;
    __half* w2s = smh + W2_OFF;
    float* b1s = (float*)(smh + HALF_END);
    float* b2s = b1s + 64;
    int*   cbuf = (int*)((char*)smh + CBUF_OFF_B);

    const unsigned smb = (unsigned)__cvta_generic_to_shared(smh);

    const int tid  = threadIdx.x;
    const int lane = tid & 31;
    const int q    = tid >> 5;
    const int kk   = lane & 3;
    const int r    = lane >> 2;

    // ---- stage weights ONCE (fp16; W1 cols permuted: feat 0..63, rel 64..66) ----
    for (int i = tid; i < 64 * W1_STR; i += 256) {
        int o = i / W1_STR, k = i - o * W1_STR;
        float w = 0.0f;
        if (k < CIN) {
            int src = (k < 64) ? (k + 3) : (k - 64);
            w = __ldg(&W1[o * CIN + src]);
        }
        w1s[i] = __float2half_rn(w);
    }
    for (int i = tid; i < 128 * W2_STR; i += 256) {
        int o = i / W2_STR, k = i - o * W2_STR;
        w2s[i] = __float2half_rn((k < H1n) ? __ldg(&W2[o * H1n + k]) : 0.0f);
    }
    if (tid < 64)  b1s[tid] = b1[tid];
    if (tid >= 128 && tid < 256) b2s[tid - 128] = b2[tid - 128];

    // zero-pad A cols 67..87 once
    {
        __half* arow = Ah + tid * A_STR;
        #pragma unroll
        for (int k = 67; k < A_STR; k++) arow[k] = __ushort_as_half(0);
    }
    __syncthreads();

    // ldmatrix lane addressing
    const int rowbase = q * 32;
    const int rr = lane & 15;
    const int ch = (lane >> 4) * 8;
    const unsigned aBase0 = smb + (unsigned)(((rowbase + rr) * A_STR + ch) * 2);
    const unsigned aBase1 = aBase0 + 16 * A_STR * 2;
    const unsigned w1Base = smb + (unsigned)((W1_OFF + rr * W1_STR + ch) * 2);
    const unsigned w2Base = smb + (unsigned)((W2_OFF + rr * W2_STR + ch) * 2);

    int* buf = cbuf + q * CAND_MAX;
    const int totwarps = NCTA * 8;
    const int gwarp = blockIdx.x * 8 + q;
    const int NQ = Bn * NP;

    // -------- ball-query state for the query currently being searched --------
    float qqx = 0.f, qqy = 0.f, qqz = 0.f;   // coords of bq-target query
    int   stq = 0, cntq = 0, ncq = 0;        // lane-resident cell descriptors
    int   offq = 0, Tq = 0, Wq = 0, Kq = 0;  // scan results / candidate count
    const float4* pbq = pts;                 // points base of bq-target batch
    int   bq_b = 0;                          // batch of bq-target query
    float4 p4[4];
    bool   act4[4];

    // gather descriptors for the bq-target query (uses qq*, bq_b)
    auto gatherDesc = [&]() {
        const int cx = min(GRID - 1, max(0, (int)(qqx * (float)GRID)));
        const int cy = min(GRID - 1, max(0, (int)(qqy * (float)GRID)));
        const int cz = min(GRID - 1, max(0, (int)(qqz * (float)GRID)));
        const int x0 = max(cx - 1, 0), x1 = min(cx + 1, GRID - 1);
        const int y0 = max(cy - 1, 0), y1 = min(cy + 1, GRID - 1);
        const int z0 = max(cz - 1, 0), z1 = min(cz + 1, GRID - 1);
        const int nx = x1 - x0 + 1, ny = y1 - y0 + 1, nz = z1 - z0 + 1;
        ncq = nx * ny * nz;
        stq = 0; cntq = 0;
        if (lane < ncq) {
            int lx = lane % nx, rem = lane / nx;
            int ly = rem % ny, lz = rem / ny;
            int c = bq_b * NCELL + (x0 + lx) + GRID * ((y0 + ly) + GRID * (z0 + lz));
            stq  = __ldg(&cellStart[c]);
            cntq = __ldg(&cellCount[c]);
        }
    };

    // warp-scan cell counts -> flat range
    auto doScan = [&]() {
        int inc = cntq;
        #pragma unroll
        for (int d = 1; d < 32; d <<= 1) {
            int t2 = __shfl_up_sync(0xffffffffu, inc, d);
            if (lane >= d) inc += t2;
        }
        offq = inc - cntq;
        Tq = __shfl_sync(0xffffffffu, inc, 31);
        Wq = (Tq + 31) >> 5;
        Kq = 0;
    };

    // batch-issue 4 waves of candidate loads (flat pos -> cell via shfl bsearch)
    auto loadB = [&](int base) {
        #pragma unroll
        for (int j = 0; j < 4; j++) {
            int f = (base + j) * 32 + lane;
            act4[j] = (base + j < Wq) && (f < Tq);
            int lo = 0, hi = ncq - 1;
            #pragma unroll
            for (int it = 0; it < 5; it++) {
                int mid = (lo + hi + 1) >> 1;
                int om = __shfl_sync(0xffffffffu, offq, mid);
                bool go = (om <= f) && (mid <= hi);
                lo = go ? mid : lo;
                hi = go ? hi : mid - 1;
            }
            int stc  = __shfl_sync(0xffffffffu, stq, lo);
            int offc = __shfl_sync(0xffffffffu, offq, lo);
            if (act4[j]) p4[j] = __ldg(&pbq[stc + (f - offc)]);
            else         p4[j] = make_float4(1e9f, 1e9f, 1e9f, 0.0f);
        }
    };

    // test + ballot-compact one batch into buf
    auto procB = [&]() {
        #pragma unroll
        for (int j = 0; j < 4; j++) {
            float dx = p4[j].x - qqx, dy = p4[j].y - qqy, dz = p4[j].z - qqz;
            float d2 = dx * dx + dy * dy + dz * dz;
            bool in = act4[j] && (d2 < RADIUS2);
            unsigned m = __ballot_sync(0xffffffffu, in);
            int pos = Kq + __popc(m & ((1u << lane) - 1u));
            if (in && pos < CAND_MAX) buf[pos] = __float_as_int(p4[j].w);
            Kq += __popc(m);
        }
    };

    // selection: min(Kq,32) smallest indices -> per-lane myid
    auto doSelect = [&]() -> int {
        __syncwarp();
        int myid;
        if (Kq <= NS) {
            myid = buf[(lane < Kq) ? lane : 0];
        } else if (Kq <= CAND_MAX) {
            int loc[(CAND_MAX + 31) / 32];
            #pragma unroll
            for (int j = 0; j < (CAND_MAX + 31) / 32; j++) {
                int p = lane + 32 * j;
                loc[j] = (p < Kq) ? buf[p] : -1;
            }
            int lmax = -1;
            #pragma unroll
            for (int j = 0; j < (CAND_MAX + 31) / 32; j++) lmax = max(lmax, loc[j]);

            const int excess = Kq - NS;
            for (int e = 0; e < excess; e++) {
                int m = lmax;
                m = max(m, __shfl_xor_sync(0xffffffffu, m, 16));
                m = max(m, __shfl_xor_sync(0xffffffffu, m, 8));
                m = max(m, __shfl_xor_sync(0xffffffffu, m, 4));
                m = max(m, __shfl_xor_sync(0xffffffffu, m, 2));
                m = max(m, __shfl_xor_sync(0xffffffffu, m, 1));
                unsigned own = __ballot_sync(0xffffffffu, lmax == m);
                if (lane == (__ffs(own) - 1)) {
                    #pragma unroll
                    for (int j = 0; j < (CAND_MAX + 31) / 32; j++)
                        if (loc[j] == m) loc[j] = -1;
                    lmax = -1;
                    #pragma unroll
                    for (int j = 0; j < (CAND_MAX + 31) / 32; j++)
                        lmax = max(lmax, loc[j]);
                }
            }
            int pos = 0;
            #pragma unroll
            for (int j = 0; j < (CAND_MAX + 31) / 32; j++) {
                bool alive = loc[j] >= 0;
                unsigned mm = __ballot_sync(0xffffffffu, alive);
                if (alive) buf[pos + __popc(mm & ((1u << lane) - 1u))] = loc[j];
                pos += __popc(mm);
            }
            __syncwarp();
            myid = buf[lane];
        } else {
            // exact fallback: ordered linear scan
            int cnt = 0, first_idx = 0;
            const float* xb = xyz + (size_t)bq_b * Nn * 3;
            for (int base = 0; base < Nn; base += 32) {
                int i = base + lane;
                float dx = __ldg(&xb[i * 3 + 0]) - qqx;
                float dy = __ldg(&xb[i * 3 + 1]) - qqy;
                float dz = __ldg(&xb[i * 3 + 2]) - qqz;
                float d2 = dx * dx + dy * dy + dz * dz;
                unsigned bits = __ballot_sync(0xffffffffu, d2 < RADIUS2);
                if (bits) {
                    if (cnt == 0) first_idx = base + __ffs(bits) - 1;
                    if ((bits >> lane) & 1u) {
                        int pos = cnt + __popc(bits & ((1u << lane) - 1u));
                        if (pos < NS) buf[pos] = i;
                    }
                    cnt += __popc(bits);
                    if (cnt >= NS) break;
                }
            }
            if (cnt < NS) {
                int slot = cnt + lane;
                if (slot < NS) buf[slot] = first_idx;
            }
            __syncwarp();
            myid = buf[lane];
        }
        return myid;
    };

    // stage this thread's A row (row = tid) for bq-target query
    auto doStage = [&](int myid) {
        const float* xb = xyz + (size_t)bq_b * Nn * 3;
        __half* arow = Ah + tid * A_STR;
        const uint4* src = (const uint4*)(g_featTh + ((size_t)bq_b * Nn + myid) * Cn);
        uint4* dst = (uint4*)arow;
        #pragma unroll
        for (int j = 0; j < 8; j++) dst[j] = __ldg(&src[j]);
        arow[64] = __float2half_rn(__ldg(&xb[myid * 3 + 0]) - qqx);
        arow[65] = __float2half_rn(__ldg(&xb[myid * 3 + 1]) - qqy);
        arow[66] = __float2half_rn(__ldg(&xb[myid * 3 + 2]) - qqz);
    };

    // ---- prologue: full ball query + staging for query 0 ----
    float qfx = 0.f, qfy = 0.f, qfz = 0.f;
    if (gwarp < NQ) {
        const int s0 = gwarp & (NP - 1);
        bq_b = gwarp >> 11;
        pbq = pts + (size_t)bq_b * Nn;
        qqx = __ldg(&xyz[((size_t)bq_b * Nn + s0) * 3 + 0]);
        qqy = __ldg(&xyz[((size_t)bq_b * Nn + s0) * 3 + 1]);
        qqz = __ldg(&xyz[((size_t)bq_b * Nn + s0) * 3 + 2]);
        if (lane < 3) {
            float v = (lane == 0) ? qqx : (lane == 1) ? qqy : qqz;
            out[(size_t)gwarp * 3 + lane] = v;
        }
        gatherDesc();
        doScan();
        int w0 = 0;
        bool pend = false;
        if (w0 < Wq) { loadB(w0); pend = true; }
        while (pend) {
            procB(); w0 += 4; pend = false;
            if (w0 < Wq) { loadB(w0); pend = true; }
        }
        int myid = doSelect();
        // load next query's point (overlaps staging)
        const int gq1 = gwarp + totwarps;
        if (gq1 < NQ) {
            const int b1_ = gq1 >> 11, s1 = gq1 & (NP - 1);
            qfx = __ldg(&xyz[((size_t)b1_ * Nn + s1) * 3 + 0]);
            qfy = __ldg(&xyz[((size_t)b1_ * Nn + s1) * 3 + 1]);
            qfz = __ldg(&xyz[((size_t)b1_ * Nn + s1) * 3 + 2]);
        }
        doStage(myid);
        qqx = qfx; qqy = qfy; qqz = qfz;
    }

    // ---- main loop: MLP(gq) interleaved with ball query(gq+totwarps) ----
    for (int gq = gwarp; gq < NQ; gq += totwarps) {
        const int b = gq >> 11;
        const int s = gq & (NP - 1);
        const int gqn = gq + totwarps;
        const bool hasNext = (gqn < NQ);
        bq_b = hasNext ? (gqn >> 11) : 0;
        pbq = pts + (size_t)bq_b * Nn;

        __syncwarp();

        // ============ Layer 1 (K=80 -> 5 k-groups) ============
        float c1[2][8][4];
        #pragma unroll
        for (int nt = 0; nt < 8; nt++) {
            float blo = b1s[nt * 8 + 2 * kk];
            float bhi = b1s[nt * 8 + 2 * kk + 1];
            #pragma unroll
            for (int mt = 0; mt < 2; mt++) {
                c1[mt][nt][0] = blo; c1[mt][nt][1] = bhi;
                c1[mt][nt][2] = blo; c1[mt][nt][3] = bhi;
            }
        }
        #pragma unroll
        for (int kg = 0; kg < 5; kg++) {
            unsigned a0[4], a1[4];
            ldsm4(a0, aBase0 + kg * 32);
            ldsm4(a1, aBase1 + kg * 32);
            #pragma unroll
            for (int p = 0; p < 4; p++) {
                unsigned bf[4];
                ldsm4(bf, w1Base + (unsigned)(16 * p * W1_STR * 2) + kg * 32);
                mma_f16(c1[0][2 * p],     a0, bf[0], bf[2]);
                mma_f16(c1[0][2 * p + 1], a0, bf[1], bf[3]);
                mma_f16(c1[1][2 * p],     a1, bf[0], bf[2]);
                mma_f16(c1[1][2 * p + 1], a1, bf[1], bf[3]);
            }
        }

        // issue next query's descriptor gather (drains under h1 store + hoist)
        if (hasNext) gatherDesc();

        __syncwarp();
        // store relu(h1) fp16 into warp-local A rows (cols 0..63)
        #pragma unroll
        for (int mt = 0; mt < 2; mt++)
            #pragma unroll
            for (int nt = 0; nt < 8; nt++)
                #pragma unroll
                for (int i = 0; i < 2; i++) {
                    int row = rowbase + mt * 16 + r + 8 * i;
                    unsigned pk = h2pack(fmaxf(c1[mt][nt][2 * i + 0], 0.0f),
                                         fmaxf(c1[mt][nt][2 * i + 1], 0.0f));
                    *(unsigned*)&Ah[row * A_STR + nt * 8 + 2 * kk] = pk;
                }
        __syncwarp();

        // hoist L2 A fragments (K=64 -> 4 k-groups); A smem dead after this
        unsigned afrag[4][8];
        #pragma unroll
        for (int kg = 0; kg < 4; kg++) {
            ldsm4(&afrag[kg][0], aBase0 + kg * 32);
            ldsm4(&afrag[kg][4], aBase1 + kg * 32);
        }

        // scan next query's counts; issue first candidate batch
        int w0 = 0;
        bool pend = false;
        if (hasNext) {
            doScan();
            if (w0 < Wq) { loadB(w0); pend = true; }
        }

        float* op_base = out + (Bn * NP * 3) + (size_t)b * H2n * NP + s;

        // ============ Layer 2 in 4 quarters of 32 outputs ============
        #pragma unroll
        for (int h = 0; h < 4; h++) {
            float c2[2][4][4];
            #pragma unroll
            for (int nt = 0; nt < 4; nt++) {
                int o = h * 32 + nt * 8;
                float blo = b2s[o + 2 * kk];
                float bhi = b2s[o + 2 * kk + 1];
                #pragma unroll
                for (int mt = 0; mt < 2; mt++) {
                    c2[mt][nt][0] = blo; c2[mt][nt][1] = bhi;
                    c2[mt][nt][2] = blo; c2[mt][nt][3] = bhi;
                }
            }
            #pragma unroll
            for (int kg = 0; kg < 4; kg++) {
                #pragma unroll
                for (int p = 0; p < 2; p++) {
                    unsigned bf[4];
                    ldsm4(bf, w2Base + (unsigned)(16 * (h * 2 + p) * W2_STR * 2) + kg * 32);
                    mma_f16(c2[0][2 * p],     &afrag[kg][0], bf[0], bf[2]);
                    mma_f16(c2[0][2 * p + 1], &afrag[kg][0], bf[1], bf[3]);
                    mma_f16(c2[1][2 * p],     &afrag[kg][4], bf[0], bf[2]);
                    mma_f16(c2[1][2 * p + 1], &afrag[kg][4], bf[1], bf[3]);
                }
            }
            // epilogue for this quarter
            #pragma unroll
            for (int nt = 0; nt < 4; nt++)
                #pragma unroll
                for (int j = 0; j < 2; j++) {
                    float v = fmaxf(fmaxf(c2[0][nt][j], c2[0][nt][j + 2]),
                                    fmaxf(c2[1][nt][j], c2[1][nt][j + 2]));
                    v = fmaxf(v, __shfl_xor_sync(0xffffffffu, v, 4));
                    v = fmaxf(v, __shfl_xor_sync(0xffffffffu, v, 8));
                    v = fmaxf(v, __shfl_xor_sync(0xffffffffu, v, 16));
                    if (r == 0) {
                        int col = h * 32 + nt * 8 + 2 * kk + j;
                        op_base[(size_t)col * NP] = fmaxf(v, 0.0f);
                    }
                }
            // interleave: consume in-flight candidate batch, issue next
            if (pend) {
                procB(); w0 += 4; pend = false;
                if (w0 < Wq) { loadB(w0); pend = true; }
            }
        }
        // drain remaining batches
        while (pend) {
            procB(); w0 += 4; pend = false;
            if (w0 < Wq) { loadB(w0); pend = true; }
        }

        // ============ tail: selection + staging for next query ============
        if (hasNext) {
            if (lane < 3) {
                float v = (lane == 0) ? qqx : (lane == 1) ? qqy : qqz;
                out[(size_t)gqn * 3 + lane] = v;
            }
            int myidn = doSelect();
            // load the query point two ahead (overlaps staging)
            const int gq2 = gqn + totwarps;
            qfx = qfy = qfz = 0.f;
            if (gq2 < NQ) {
                const int b2_ = gq2 >> 11, s2 = gq2 & (NP - 1);
                qfx = __ldg(&xyz[((size_t)b2_ * Nn + s2) * 3 + 0]);
                qfy = __ldg(&xyz[((size_t)b2_ * Nn + s2) * 3 + 1]);
                qfz = __ldg(&xyz[((size_t)b2_ * Nn + s2) * 3 + 2]);
            }
            doStage(myidn);
            qqx = qfx; qqy = qfy; qqz = qfz;
        }
    }
}

// ---------------------------------------------------------------------------
extern "C" void kernel_launch(void* const* d_in, const int* in_sizes, int n_in,
                              void* d_out, int out_size)
{
    const float* xyz      = (const float*)d_in[0];
    const float* features = (const float*)d_in[1];
    const float* W1       = (const float*)d_in[2];
    const float* b1       = (const float*)d_in[3];
    const float* W2       = (const float*)d_in[4];
    const float* b2       = (const float*)d_in[5];
    float* out = (float*)d_out;

    static bool init_done = false;
    static cudaStream_t s2;
    static cudaEvent_t eFork, eJoin;
    if (!init_done) {
        cudaFuncSetAttribute(fused_kernel, cudaFuncAttributeMaxDynamicSharedMemorySize,
                             SMEM_BYTES);
        cudaStreamCreateWithFlags(&s2, cudaStreamNonBlocking);
        cudaEventCreateWithFlags(&eFork, cudaEventDisableTiming);
        cudaEventCreateWithFlags(&eJoin, cudaEventDisableTiming);
        init_done = true;
    }

    __half* fthp;   cudaGetSymbolAddress((void**)&fthp, g_featTh);
    float4* ptsp;   cudaGetSymbolAddress((void**)&ptsp, g_pts);
    int*    cntp;   cudaGetSymbolAddress((void**)&cntp, g_cellCount);
    int*    stp;    cudaGetSymbolAddress((void**)&stp,  g_cellStart);

    // Fork: transpose (depends only on features) on s2, parallel to binning.
    cudaEventRecord(eFork, 0);
    cudaStreamWaitEvent(s2, eFork, 0);
    {
        dim3 blk(256, 1, 1);
        dim3 grd(Nn / 64, Cn / 32, Bn);
        transpose_kernel<<<grd, blk, 0, s2>>>(features, fthp);
    }
    cudaEventRecord(eJoin, s2);

    // Main stream: single-kernel binning
    bin_all_kernel<<<Bn, 1024>>>(xyz, ptsp, stp, cntp);

    // Join, then fused persistent ball-query + MLP + max
    cudaStreamWaitEvent(0, eJoin, 0);
    fused_kernel<<<NCTA, 256, SMEM_BYTES>>>(xyz, ptsp, stp, cntp,
                                            W1, b1, W2, b2, out);
}

// round 17
// speedup vs baseline: 1.1142x; 1.1142x over previous
#include <cuda_runtime.h>
#include <cuda_fp16.h>
#include <cstdint>

// Problem constants (fixed shapes per reference setup_inputs)
#define Bn      8
#define Nn      8192
#define Cn      64
#define NP      2048
#define NS      32
#define CIN     67
#define H1n     64
#define H2n     128
#define RADIUS2 0.01f

#define GRID    8
#define NCELL   (GRID * GRID * GRID)     // 512 per batch
#define CAND_MAX 288
#define NCTA    296                      // persistent: 2 CTAs x 148 SMs

// Scratch (allocation-free rule: __device__ globals)
__device__ __half g_featTh[(size_t)Bn * Nn * Cn];      // 8 MB, (B,N,C) fp16
__device__ float4 g_pts[Bn * Nn];                      // 1 MB cell-sorted pts
__device__ int    g_cellCount[Bn * NCELL];
__device__ int    g_cellStart[Bn * NCELL];

typedef unsigned long long ull;

// ---------------------------------------------------------------------------
// fp16 mma / ldmatrix helpers
// ---------------------------------------------------------------------------
__device__ __forceinline__ void mma_f16(float c[4], const unsigned a[4],
                                        unsigned b0, unsigned b1)
{
    asm volatile(
        "mma.sync.aligned.m16n8k16.row.col.f32.f16.f16.f32 "
        "{%0,%1,%2,%3}, {%4,%5,%6,%7}, {%8,%9}, {%0,%1,%2,%3};"
        : "+f"(c[0]), "+f"(c[1]), "+f"(c[2]), "+f"(c[3])
        : "r"(a[0]), "r"(a[1]), "r"(a[2]), "r"(a[3]), "r"(b0), "r"(b1));
}

__device__ __forceinline__ void ldsm4(unsigned* r, unsigned addr)
{
    asm volatile("ldmatrix.sync.aligned.m8n8.x4.shared.b16 {%0,%1,%2,%3}, [%4];"
                 : "=r"(r[0]), "=r"(r[1]), "=r"(r[2]), "=r"(r[3]) : "r"(addr));
}

__device__ __forceinline__ unsigned h2pack(float lo, float hi)
{
    __half2 h = __floats2half2_rn(lo, hi);
    return *(unsigned*)&h;
}

__device__ __forceinline__ int cell_of(float x, float y, float z)
{
    int cx = min(GRID - 1, max(0, (int)(x * (float)GRID)));
    int cy = min(GRID - 1, max(0, (int)(y * (float)GRID)));
    int cz = min(GRID - 1, max(0, (int)(z * (float)GRID)));
    return cx + GRID * (cy + GRID * cz);
}

// ---------------------------------------------------------------------------
// Single-kernel binning: one 1024-thread CTA per batch.
// ---------------------------------------------------------------------------
__global__ __launch_bounds__(1024) void bin_all_kernel(
    const float* __restrict__ xyz,
    float4* __restrict__ pts,
    int* __restrict__ cellStart, int* __restrict__ cellCount)
{
    __shared__ int sc[NCELL];
    __shared__ int scur[NCELL];

    const int b = blockIdx.x;
    const int t = threadIdx.x;          // 0..1023, 8 points per thread

    if (t < NCELL) sc[t] = 0;
    __syncthreads();

    const float* xb = xyz + (size_t)b * Nn * 3;
    float px[8], py[8], pz[8];
    int   pc[8];

    #pragma unroll
    for (int j = 0; j < 8; j++) {
        int i = t + j * 1024;
        px[j] = xb[i * 3 + 0];
        py[j] = xb[i * 3 + 1];
        pz[j] = xb[i * 3 + 2];
        pc[j] = cell_of(px[j], py[j], pz[j]);
        atomicAdd(&sc[pc[j]], 1);
    }
    __syncthreads();

    int c0 = (t < NCELL) ? sc[t] : 0;
    for (int off = 1; off < NCELL; off <<= 1) {
        int v = 0;
        if (t < NCELL && t >= off) v = sc[t - off];
        __syncthreads();
        if (t < NCELL) sc[t] += v;
        __syncthreads();
    }
    if (t < NCELL) {
        int excl = sc[t] - c0;
        cellStart[b * NCELL + t] = excl;
        cellCount[b * NCELL + t] = c0;
        scur[t] = excl;
    }
    __syncthreads();

    float4* pout = pts + (size_t)b * Nn;
    #pragma unroll
    for (int j = 0; j < 8; j++) {
        int i = t + j * 1024;
        int pos = atomicAdd(&scur[pc[j]], 1);
        pout[pos] = make_float4(px[j], py[j], pz[j], __int_as_float(i));
    }
}

// ---------------------------------------------------------------------------
// Transpose features (B,C,N) f32 -> (B,N,C) fp16, vectorized.
// ---------------------------------------------------------------------------
__global__ __launch_bounds__(256) void transpose_kernel(
    const float* __restrict__ f, __half* __restrict__ ft)
{
    __shared__ float tile[64][33];
    const int b  = blockIdx.z;
    const int c0 = blockIdx.y * 32;
    const int n0 = blockIdx.x * 64;
    const int t  = threadIdx.x;

    const float* fb = f + (size_t)b * Cn * Nn;

    #pragma unroll
    for (int j = 0; j < 2; j++) {
        int idx = t + j * 256;
        int c   = idx >> 4;
        int n4  = (idx & 15) * 4;
        float4 v = __ldg((const float4*)&fb[(size_t)(c0 + c) * Nn + n0 + n4]);
        tile[n4 + 0][c] = v.x;
        tile[n4 + 1][c] = v.y;
        tile[n4 + 2][c] = v.z;
        tile[n4 + 3][c] = v.w;
    }
    __syncthreads();

    __half* fo = ft + (size_t)b * Nn * Cn;
    #pragma unroll
    for (int j = 0; j < 2; j++) {
        int idx = t + j * 256;
        int n   = idx >> 3;
        int c4  = (idx & 7) * 4;
        unsigned lo = h2pack(tile[n][c4 + 0], tile[n][c4 + 1]);
        unsigned hi = h2pack(tile[n][c4 + 2], tile[n][c4 + 3]);
        ull pk = (ull)lo | ((ull)hi << 32);
        *(ull*)&fo[(size_t)(n0 + n) * Cn + c0 + c4] = pk;
    }
}

// ---------------------------------------------------------------------------
// FUSED persistent kernel: grid ball query + group + MLP + max.
// R17: R15 structure (known-good) + double-buffered 4-wave candidate batches
// (issue batch k+1 before processing batch k; register-neutral vs R15).
// ---------------------------------------------------------------------------
#define A_STR   88
#define W1_STR  88
#define W2_STR  72
#define A_OFF   0
#define W1_OFF  (256 * A_STR)               // 22528 halfs
#define W2_OFF  (W1_OFF + 64 * W1_STR)      // 28160
#define HALF_END (W2_OFF + 128 * W2_STR)    // 37376 halfs = 74752 B
#define BIAS_BYTES ((64 + 128) * 4)
#define CBUF_OFF_B (HALF_END * 2 + BIAS_BYTES)
#define SMEM_BYTES (CBUF_OFF_B + 8 * CAND_MAX * 4)

// batch-issue 4 waves of candidate loads (flat pos -> cell via shfl bsearch)
#define LOADB(P, ACT, BASE)                                              \
    _Pragma("unroll")                                                    \
    for (int j = 0; j < 4; j++) {                                        \
        int f = ((BASE) + j) * 32 + lane;                                \
        (ACT)[j] = (((BASE) + j) < W) && (f < T);                        \
        int lo = 0, hi = ncells - 1;                                     \
        _Pragma("unroll")                                                \
        for (int it = 0; it < 5; it++) {                                 \
            int mid = (lo + hi + 1) >> 1;                                \
            int om = __shfl_sync(0xffffffffu, off, mid);                 \
            bool go = (om <= f) && (mid <= hi);                          \
            lo = go ? mid : lo;                                          \
            hi = go ? hi : mid - 1;                                      \
        }                                                                \
        int stc  = __shfl_sync(0xffffffffu, stL, lo);                    \
        int offc = __shfl_sync(0xffffffffu, off, lo);                    \
        if ((ACT)[j]) (P)[j] = __ldg(&pb[stc + (f - offc)]);             \
        else          (P)[j] = make_float4(1e9f, 1e9f, 1e9f, 0.0f);      \
    }

__global__ __launch_bounds__(256, 2) void fused_kernel(
    const float*  __restrict__ xyz,
    const float4* __restrict__ pts,
    const int*    __restrict__ cellStart,
    const int*    __restrict__ cellCount,
    const float*  __restrict__ W1,
    const float*  __restrict__ b1,
    const float*  __restrict__ W2,
    const float*  __restrict__ b2,
    float* __restrict__ out)
{
    extern __shared__ __half smh[];
    __half* Ah  = smh + A_OFF;
    __half* w1s = smh + W1_OFF;
    __half* w2s = smh + W2_OFF;
    float* b1s = (float*)(smh + HALF_END);
    float* b2s = b1s + 64;
    int*   cbuf = (int*)((char*)smh + CBUF_OFF_B);

    const unsigned smb = (unsigned)__cvta_generic_to_shared(smh);

    const int tid  = threadIdx.x;
    const int lane = tid & 31;
    const int q    = tid >> 5;
    const int kk   = lane & 3;
    const int r    = lane >> 2;

    // ---- stage weights ONCE (fp16; W1 cols permuted: feat 0..63, rel 64..66) ----
    for (int i = tid; i < 64 * W1_STR; i += 256) {
        int o = i / W1_STR, k = i - o * W1_STR;
        float w = 0.0f;
        if (k < CIN) {
            int src = (k < 64) ? (k + 3) : (k - 64);
            w = __ldg(&W1[o * CIN + src]);
        }
        w1s[i] = __float2half_rn(w);
    }
    for (int i = tid; i < 128 * W2_STR; i += 256) {
        int o = i / W2_STR, k = i - o * W2_STR;
        w2s[i] = __float2half_rn((k < H1n) ? __ldg(&W2[o * H1n + k]) : 0.0f);
    }
    if (tid < 64)  b1s[tid] = b1[tid];
    if (tid >= 128 && tid < 256) b2s[tid - 128] = b2[tid - 128];

    // zero-pad A cols 67..87 once
    {
        __half* arow = Ah + tid * A_STR;
        #pragma unroll
        for (int k = 67; k < A_STR; k++) arow[k] = __ushort_as_half(0);
    }
    __syncthreads();

    // ldmatrix lane addressing
    const int rowbase = q * 32;
    const int rr = lane & 15;
    const int ch = (lane >> 4) * 8;
    const unsigned aBase0 = smb + (unsigned)(((rowbase + rr) * A_STR + ch) * 2);
    const unsigned aBase1 = aBase0 + 16 * A_STR * 2;
    const unsigned w1Base = smb + (unsigned)((W1_OFF + rr * W1_STR + ch) * 2);
    const unsigned w2Base = smb + (unsigned)((W2_OFF + rr * W2_STR + ch) * 2);

    int* buf = cbuf + q * CAND_MAX;
    const int totwarps = NCTA * 8;
    const int gwarp = blockIdx.x * 8 + q;
    const int NQ = Bn * NP;

    // ---- pipeline prologue: load query 0's point + descriptors ----
    float qx = 0.f, qy = 0.f, qz = 0.f;
    int stL = 0, cntL = 0, ncells = 0;
    if (gwarp < NQ) {
        const int b0 = gwarp >> 11, s0 = gwarp & (NP - 1);
        qx = __ldg(&xyz[((size_t)b0 * Nn + s0) * 3 + 0]);
        qy = __ldg(&xyz[((size_t)b0 * Nn + s0) * 3 + 1]);
        qz = __ldg(&xyz[((size_t)b0 * Nn + s0) * 3 + 2]);
        const int cx = min(GRID - 1, max(0, (int)(qx * (float)GRID)));
        const int cy = min(GRID - 1, max(0, (int)(qy * (float)GRID)));
        const int cz = min(GRID - 1, max(0, (int)(qz * (float)GRID)));
        const int x0 = max(cx - 1, 0), x1 = min(cx + 1, GRID - 1);
        const int y0 = max(cy - 1, 0), y1 = min(cy + 1, GRID - 1);
        const int z0 = max(cz - 1, 0), z1 = min(cz + 1, GRID - 1);
        const int nx = x1 - x0 + 1, ny = y1 - y0 + 1, nz = z1 - z0 + 1;
        ncells = nx * ny * nz;
        if (lane < ncells) {
            int lx = lane % nx, rem = lane / nx;
            int ly = rem % ny, lz = rem / ny;
            int c = b0 * NCELL + (x0 + lx) + GRID * ((y0 + ly) + GRID * (z0 + lz));
            stL  = __ldg(&cellStart[c]);
            cntL = __ldg(&cellCount[c]);
        }
    }

    for (int gq = gwarp; gq < NQ; gq += totwarps) {
        const int b = gq >> 11;              // NP = 2048
        const int s = gq & (NP - 1);

        if (lane < 3) {
            float v = (lane == 0) ? qx : (lane == 1) ? qy : qz;
            out[(size_t)gq * 3 + lane] = v;
        }

        // warp exclusive scan of counts -> flat candidate range [0, T)
        int inc = cntL;
        #pragma unroll
        for (int d = 1; d < 32; d <<= 1) {
            int t2 = __shfl_up_sync(0xffffffffu, inc, d);
            if (lane >= d) inc += t2;
        }
        const int off = inc - cntL;                       // exclusive prefix
        const int T = __shfl_sync(0xffffffffu, inc, 31);  // total candidates

        int K = 0;
        const float4* pb = pts + (size_t)b * Nn;
        const int W = (T + 31) >> 5;                      // 32-wide waves

        // double-buffered 4-wave batches: issue k+1 before processing k
        {
            float4 pA[4], pB[4];
            bool   actA[4], actB[4];
            if (W > 0) { LOADB(pA, actA, 0); }
            for (int w0 = 0; w0 < W; w0 += 4) {
                if (w0 + 4 < W) { LOADB(pB, actB, w0 + 4); }
                #pragma unroll
                for (int j = 0; j < 4; j++) {
                    float dx = pA[j].x - qx, dy = pA[j].y - qy, dz = pA[j].z - qz;
                    float d2 = dx * dx + dy * dy + dz * dz;
                    bool in = actA[j] && (d2 < RADIUS2);
                    unsigned m = __ballot_sync(0xffffffffu, in);
                    int pos = K + __popc(m & ((1u << lane) - 1u));
                    if (in && pos < CAND_MAX) buf[pos] = __float_as_int(pA[j].w);
                    K += __popc(m);
                }
                #pragma unroll
                for (int j = 0; j < 4; j++) { pA[j] = pB[j]; actA[j] = actB[j]; }
            }
        }
        __syncwarp();

        int myid;
        if (K <= NS) {
            myid = buf[(lane < K) ? lane : 0];
        } else if (K <= CAND_MAX) {
            // drop-max selection: remove the K-NS largest (expected ~2-8)
            int loc[(CAND_MAX + 31) / 32];
            #pragma unroll
            for (int j = 0; j < (CAND_MAX + 31) / 32; j++) {
                int p = lane + 32 * j;
                loc[j] = (p < K) ? buf[p] : -1;
            }
            int lmax = -1;
            #pragma unroll
            for (int j = 0; j < (CAND_MAX + 31) / 32; j++) lmax = max(lmax, loc[j]);

            const int excess = K - NS;
            for (int e = 0; e < excess; e++) {
                int m = lmax;
                m = max(m, __shfl_xor_sync(0xffffffffu, m, 16));
                m = max(m, __shfl_xor_sync(0xffffffffu, m, 8));
                m = max(m, __shfl_xor_sync(0xffffffffu, m, 4));
                m = max(m, __shfl_xor_sync(0xffffffffu, m, 2));
                m = max(m, __shfl_xor_sync(0xffffffffu, m, 1));
                unsigned own = __ballot_sync(0xffffffffu, lmax == m);
                if (lane == (__ffs(own) - 1)) {
                    #pragma unroll
                    for (int j = 0; j < (CAND_MAX + 31) / 32; j++)
                        if (loc[j] == m) loc[j] = -1;      // indices distinct
                    lmax = -1;
                    #pragma unroll
                    for (int j = 0; j < (CAND_MAX + 31) / 32; j++)
                        lmax = max(lmax, loc[j]);
                }
            }
            int pos = 0;
            #pragma unroll
            for (int j = 0; j < (CAND_MAX + 31) / 32; j++) {
                bool alive = loc[j] >= 0;
                unsigned mm = __ballot_sync(0xffffffffu, alive);
                if (alive) buf[pos + __popc(mm & ((1u << lane) - 1u))] = loc[j];
                pos += __popc(mm);
            }
            __syncwarp();
            myid = buf[lane];
        } else {
            // exact fallback: ordered linear scan into buf
            int cnt = 0, first_idx = 0;
            const float* xb = xyz + (size_t)b * Nn * 3;
            for (int base = 0; base < Nn; base += 32) {
                int i = base + lane;
                float dx = __ldg(&xb[i * 3 + 0]) - qx;
                float dy = __ldg(&xb[i * 3 + 1]) - qy;
                float dz = __ldg(&xb[i * 3 + 2]) - qz;
                float d2 = dx * dx + dy * dy + dz * dz;
                unsigned bits = __ballot_sync(0xffffffffu, d2 < RADIUS2);
                if (bits) {
                    if (cnt == 0) first_idx = base + __ffs(bits) - 1;
                    if ((bits >> lane) & 1u) {
                        int pos = cnt + __popc(bits & ((1u << lane) - 1u));
                        if (pos < NS) buf[pos] = i;
                    }
                    cnt += __popc(bits);
                    if (cnt >= NS) break;
                }
            }
            if (cnt < NS) {
                int slot = cnt + lane;
                if (slot < NS) buf[slot] = first_idx;
            }
            __syncwarp();
            myid = buf[lane];
        }

        // ---- pipeline: issue NEXT query's point load (independent of MLP) ----
        const int gqn = gq + totwarps;
        float qxn = 0.f, qyn = 0.f, qzn = 0.f;
        if (gqn < NQ) {
            const int bn = gqn >> 11, sn = gqn & (NP - 1);
            qxn = __ldg(&xyz[((size_t)bn * Nn + sn) * 3 + 0]);
            qyn = __ldg(&xyz[((size_t)bn * Nn + sn) * 3 + 1]);
            qzn = __ldg(&xyz[((size_t)bn * Nn + sn) * 3 + 2]);
        }

        // ================== stage A row (LDG.128 x8) ==================
        {
            const float* xb = xyz + (size_t)b * Nn * 3;
            __half* arow = Ah + tid * A_STR;
            const uint4* src = (const uint4*)(g_featTh + ((size_t)b * Nn + myid) * Cn);
            uint4* dst = (uint4*)arow;
            #pragma unroll
            for (int j = 0; j < 8; j++) dst[j] = __ldg(&src[j]);
            arow[64] = __float2half_rn(__ldg(&xb[myid * 3 + 0]) - qx);
            arow[65] = __float2half_rn(__ldg(&xb[myid * 3 + 1]) - qy);
            arow[66] = __float2half_rn(__ldg(&xb[myid * 3 + 2]) - qz);
        }
        __syncwarp();

        // ================== Layer 1 (K=80 -> 5 k-groups) ==================
        float c1[2][8][4];
        #pragma unroll
        for (int nt = 0; nt < 8; nt++) {
            float blo = b1s[nt * 8 + 2 * kk];
            float bhi = b1s[nt * 8 + 2 * kk + 1];
            #pragma unroll
            for (int mt = 0; mt < 2; mt++) {
                c1[mt][nt][0] = blo; c1[mt][nt][1] = bhi;
                c1[mt][nt][2] = blo; c1[mt][nt][3] = bhi;
            }
        }

        #pragma unroll
        for (int kg = 0; kg < 5; kg++) {
            unsigned a0[4], a1[4];
            ldsm4(a0, aBase0 + kg * 32);
            ldsm4(a1, aBase1 + kg * 32);
            #pragma unroll
            for (int p = 0; p < 4; p++) {
                unsigned bf[4];
                ldsm4(bf, w1Base + (unsigned)(16 * p * W1_STR * 2) + kg * 32);
                mma_f16(c1[0][2 * p],     a0, bf[0], bf[2]);
                mma_f16(c1[0][2 * p + 1], a0, bf[1], bf[3]);
                mma_f16(c1[1][2 * p],     a1, bf[0], bf[2]);
                mma_f16(c1[1][2 * p + 1], a1, bf[1], bf[3]);
            }
        }
        __syncwarp();

        // ---- pipeline: issue NEXT query's descriptor gather (point arrived) ----
        int stLn = 0, cntLn = 0, ncellsn = 0;
        if (gqn < NQ) {
            const int bn = gqn >> 11;
            const int cx = min(GRID - 1, max(0, (int)(qxn * (float)GRID)));
            const int cy = min(GRID - 1, max(0, (int)(qyn * (float)GRID)));
            const int cz = min(GRID - 1, max(0, (int)(qzn * (float)GRID)));
            const int x0 = max(cx - 1, 0), x1 = min(cx + 1, GRID - 1);
            const int y0 = max(cy - 1, 0), y1 = min(cy + 1, GRID - 1);
            const int z0 = max(cz - 1, 0), z1 = min(cz + 1, GRID - 1);
            const int nx = x1 - x0 + 1, ny = y1 - y0 + 1, nz = z1 - z0 + 1;
            ncellsn = nx * ny * nz;
            if (lane < ncellsn) {
                int lx = lane % nx, rem = lane / nx;
                int ly = rem % ny, lz = rem / ny;
                int c = bn * NCELL + (x0 + lx) + GRID * ((y0 + ly) + GRID * (z0 + lz));
                stLn  = __ldg(&cellStart[c]);
                cntLn = __ldg(&cellCount[c]);
            }
        }

        // store relu(h1) fp16 into warp-local A rows (cols 0..63)
        #pragma unroll
        for (int mt = 0; mt < 2; mt++)
            #pragma unroll
            for (int nt = 0; nt < 8; nt++)
                #pragma unroll
                for (int i = 0; i < 2; i++) {
                    int row = rowbase + mt * 16 + r + 8 * i;
                    unsigned pk = h2pack(fmaxf(c1[mt][nt][2 * i + 0], 0.0f),
                                         fmaxf(c1[mt][nt][2 * i + 1], 0.0f));
                    *(unsigned*)&Ah[row * A_STR + nt * 8 + 2 * kk] = pk;
                }
        __syncwarp();

        // hoist L2 A fragments (K=64 -> 4 k-groups)
        unsigned afrag[4][8];
        #pragma unroll
        for (int kg = 0; kg < 4; kg++) {
            ldsm4(&afrag[kg][0], aBase0 + kg * 32);
            ldsm4(&afrag[kg][4], aBase1 + kg * 32);
        }

        float* op_base = out + (Bn * NP * 3) + (size_t)b * H2n * NP + s;

        #pragma unroll
        for (int h = 0; h < 2; h++) {
            float c2[2][8][4];
            #pragma unroll
            for (int nt = 0; nt < 8; nt++) {
                int o = h * 64 + nt * 8;
                float blo = b2s[o + 2 * kk];
                float bhi = b2s[o + 2 * kk + 1];
                #pragma unroll
                for (int mt = 0; mt < 2; mt++) {
                    c2[mt][nt][0] = blo; c2[mt][nt][1] = bhi;
                    c2[mt][nt][2] = blo; c2[mt][nt][3] = bhi;
                }
            }

            #pragma unroll
            for (int kg = 0; kg < 4; kg++) {
                #pragma unroll
                for (int p = 0; p < 4; p++) {
                    unsigned bf[4];
                    ldsm4(bf, w2Base + (unsigned)(16 * (h * 4 + p) * W2_STR * 2) + kg * 32);
                    mma_f16(c2[0][2 * p],     &afrag[kg][0], bf[0], bf[2]);
                    mma_f16(c2[0][2 * p + 1], &afrag[kg][0], bf[1], bf[3]);
                    mma_f16(c2[1][2 * p],     &afrag[kg][4], bf[0], bf[2]);
                    mma_f16(c2[1][2 * p + 1], &afrag[kg][4], bf[1], bf[3]);
                }
            }

            #pragma unroll
            for (int nt = 0; nt < 8; nt++)
                #pragma unroll
                for (int j = 0; j < 2; j++) {
                    float v = fmaxf(fmaxf(c2[0][nt][j], c2[0][nt][j + 2]),
                                    fmaxf(c2[1][nt][j], c2[1][nt][j + 2]));
                    v = fmaxf(v, __shfl_xor_sync(0xffffffffu, v, 4));
                    v = fmaxf(v, __shfl_xor_sync(0xffffffffu, v, 8));
                    v = fmaxf(v, __shfl_xor_sync(0xffffffffu, v, 16));
                    if (r == 0) {
                        int col = h * 64 + nt * 8 + 2 * kk + j;
                        op_base[(size_t)col * NP] = fmaxf(v, 0.0f);
                    }
                }
        }
        __syncwarp();   // h1/A reads done before next iteration restages

        // ---- rotate pipeline registers ----
        qx = qxn; qy = qyn; qz = qzn;
        stL = stLn; cntL = cntLn; ncells = ncellsn;
    }
}

// ---------------------------------------------------------------------------
extern "C" void kernel_launch(void* const* d_in, const int* in_sizes, int n_in,
                              void* d_out, int out_size)
{
    const float* xyz      = (const float*)d_in[0];
    const float* features = (const float*)d_in[1];
    const float* W1       = (const float*)d_in[2];
    const float* b1       = (const float*)d_in[3];
    const float* W2       = (const float*)d_in[4];
    const float* b2       = (const float*)d_in[5];
    float* out = (float*)d_out;

    static bool init_done = false;
    static cudaStream_t s2;
    static cudaEvent_t eFork, eJoin;
    if (!init_done) {
        cudaFuncSetAttribute(fused_kernel, cudaFuncAttributeMaxDynamicSharedMemorySize,
                             SMEM_BYTES);
        cudaStreamCreateWithFlags(&s2, cudaStreamNonBlocking);
        cudaEventCreateWithFlags(&eFork, cudaEventDisableTiming);
        cudaEventCreateWithFlags(&eJoin, cudaEventDisableTiming);
        init_done = true;
    }

    __half* fthp;   cudaGetSymbolAddress((void**)&fthp, g_featTh);
    float4* ptsp;   cudaGetSymbolAddress((void**)&ptsp, g_pts);
    int*    cntp;   cudaGetSymbolAddress((void**)&cntp, g_cellCount);
    int*    stp;    cudaGetSymbolAddress((void**)&stp,  g_cellStart);

    // Fork: transpose (depends only on features) on s2, parallel to binning.
    cudaEventRecord(eFork, 0);
    cudaStreamWaitEvent(s2, eFork, 0);
    {
        dim3 blk(256, 1, 1);
        dim3 grd(Nn / 64, Cn / 32, Bn);
        transpose_kernel<<<grd, blk, 0, s2>>>(features, fthp);
    }
    cudaEventRecord(eJoin, s2);

    // Main stream: single-kernel binning
    bin_all_kernel<<<Bn, 1024>>>(xyz, ptsp, stp, cntp);

    // Join, then fused persistent ball-query + MLP + max
    cudaStreamWaitEvent(0, eJoin, 0);
    fused_kernel<<<NCTA, 256, SMEM_BYTES>>>(xyz, ptsp, stp, cntp,
                                            W1, b1, W2, b2, out);
}